// round 12
// baseline (speedup 1.0000x reference)
#include <cuda_runtime.h>
#include <cstddef>
#include <cstdint>

// FusionAdjacency: Af = rownorm( sigmoid(g)*scatter(s) + (1-sigmoid(g))*scatter(t) )
//
// R10: touched-word bitmap removes the fill->scatter ordering, so the scatter
// folds homogeneously into the DRAM-write-bound fill kernel (proven ~free in
// R8 for the hist fold). Fill skips words whose bitmap bit is set; scatter
// REDs target exactly those words -> disjoint addresses, no ordering needed.
//   K0: zero 8MB bitmap
//   K1: per edge: out[r,c]=0 (idempotent), atomicOr bitmap bit, hist RED
//   K2: rowinv = guarded reciprocal; re-zero rowsum (replay-safe)
//   K3: folded scatter REDs + bitmap-guided zero-fill of everything else

#define NN 8192
#define NWORDS ((NN * NN) / 32)   // 2,097,152 bitmap words = 8 MB

__device__ uint32_t g_bitmap[NWORDS];
__device__ float    g_rowsum[NN];   // zeroed at load; K2 re-zeros each call
__device__ float    g_rowinv[NN];

// ---------------------------------------------------------------- K0
__global__ __launch_bounds__(256) void k0_zero_bitmap() {
    const int tid = blockIdx.x * blockDim.x + threadIdx.x;
    const int stride = gridDim.x * blockDim.x;
    uint4* bm4 = reinterpret_cast<uint4*>(g_bitmap);
    const int n4 = NWORDS / 4;
    const uint4 z = make_uint4(0u, 0u, 0u, 0u);
    for (int i = tid; i < n4; i += stride) bm4[i] = z;
}

// ---------------------------------------------------------------- K1
__global__ __launch_bounds__(256) void k1_touch_hist(
        const int* __restrict__ rows_s, const int* __restrict__ cols_s,
        const float* __restrict__ vals_s, int Es,
        const int* __restrict__ rows_t, const int* __restrict__ cols_t,
        const float* __restrict__ vals_t, int Et,
        const float* __restrict__ gamma, float* __restrict__ out) {
    const int tid = blockIdx.x * blockDim.x + threadIdx.x;
    const int stride = gridDim.x * blockDim.x;
    const float g = gamma[0];
    const float alpha = 1.0f / (1.0f + expf(-g));
    const float beta = 1.0f - alpha;

    for (int e = tid; e < Es; e += stride) {
        int r = __ldg(&rows_s[e]);
        int c = __ldg(&cols_s[e]);
        size_t idx = ((size_t)r << 13) + c;
        out[idx] = 0.0f;                                   // idempotent zero
        atomicOr(&g_bitmap[idx >> 5], 1u << (idx & 31));   // mark touched
        atomicAdd(&g_rowsum[r], alpha * __ldg(&vals_s[e]));
    }
    for (int e = tid; e < Et; e += stride) {
        int r = __ldg(&rows_t[e]);
        int c = __ldg(&cols_t[e]);
        size_t idx = ((size_t)r << 13) + c;
        out[idx] = 0.0f;
        atomicOr(&g_bitmap[idx >> 5], 1u << (idx & 31));
        atomicAdd(&g_rowsum[r], beta * __ldg(&vals_t[e]));
    }
}

// ---------------------------------------------------------------- K2
__global__ void k2_finalize() {
    int i = blockIdx.x * blockDim.x + threadIdx.x;
    if (i < NN) {
        float s = g_rowsum[i];
        g_rowinv[i] = (s == 0.0f) ? 1.0f : (1.0f / s);
        g_rowsum[i] = 0.0f;   // ready for next graph replay
    }
}

// ---------------------------------------------------------------- K3
// Folded scatter (fire-and-forget REDs into bit-set words, zeroed by K1)
// + bitmap-guided fill (writes only bit-clear words). Disjoint addresses.
__global__ __launch_bounds__(256) void k3_fill_scatter(
        const int* __restrict__ rows_s, const int* __restrict__ cols_s,
        const float* __restrict__ vals_s, int Es,
        const int* __restrict__ rows_t, const int* __restrict__ cols_t,
        const float* __restrict__ vals_t, int Et,
        const float* __restrict__ gamma, float* __restrict__ out) {
    const int tid = blockIdx.x * blockDim.x + threadIdx.x;
    const int stride = gridDim.x * blockDim.x;
    const float g = gamma[0];
    const float alpha = 1.0f / (1.0f + expf(-g));
    const float beta = 1.0f - alpha;

    // ---- scatter fold: <=1 edge per thread per list; REDs drain under fill
    for (int e = tid; e < Es; e += stride) {
        int r = __ldg(&rows_s[e]);
        float contrib = alpha * __ldg(&vals_s[e]) * g_rowinv[r];
        atomicAdd(&out[((size_t)r << 13) + __ldg(&cols_s[e])], contrib);
    }
    for (int e = tid; e < Et; e += stride) {
        int r = __ldg(&rows_t[e]);
        float contrib = beta * __ldg(&vals_t[e]) * g_rowinv[r];
        atomicAdd(&out[((size_t)r << 13) + __ldg(&cols_t[e])], contrib);
    }

    // ---- fill: one 128B line (32 floats, 1 bitmap word) per iteration
    const float4 z4 = make_float4(0.f, 0.f, 0.f, 0.f);
    for (int L = tid; L < NWORDS; L += stride) {
        uint32_t w = __ldg(&g_bitmap[L]);
        float4* p4 = reinterpret_cast<float4*>(out) + (size_t)L * 8;
        if (w == 0u) {
            // untouched line (~78%): pure streaming zero
#pragma unroll
            for (int j = 0; j < 8; j++) __stcs(&p4[j], z4);
        } else {
            // touched line: store only words whose bit is clear
            float* pw = out + (size_t)L * 32;
#pragma unroll
            for (int j = 0; j < 8; j++) {
                uint32_t nb = (w >> (j * 4)) & 0xFu;
                if (nb == 0u) {
                    __stcs(&p4[j], z4);
                } else {
                    if (!(nb & 1u)) __stcs(&pw[j * 4 + 0], 0.0f);
                    if (!(nb & 2u)) __stcs(&pw[j * 4 + 1], 0.0f);
                    if (!(nb & 4u)) __stcs(&pw[j * 4 + 2], 0.0f);
                    if (!(nb & 8u)) __stcs(&pw[j * 4 + 3], 0.0f);
                }
            }
        }
    }
}

// ---------------------------------------------------------------- launch
extern "C" void kernel_launch(void* const* d_in, const int* in_sizes, int n_in,
                              void* d_out, int out_size) {
    const int*   rows_s = (const int*)d_in[0];
    const int*   cols_s = (const int*)d_in[1];
    const float* vals_s = (const float*)d_in[2];
    const int*   rows_t = (const int*)d_in[3];
    const int*   cols_t = (const int*)d_in[4];
    const float* vals_t = (const float*)d_in[5];
    const float* gamma  = (const float*)d_in[6];
    float* out = (float*)d_out;

    const int Es = in_sizes[0];
    const int Et = in_sizes[3];
    const int T = 256;

    k0_zero_bitmap<<<1184, T>>>();

    k1_touch_hist<<<2048, T>>>(rows_s, cols_s, vals_s, Es,
                               rows_t, cols_t, vals_t, Et, gamma, out);

    k2_finalize<<<(NN + 255) / 256, 256>>>();

    k3_fill_scatter<<<2368, T>>>(rows_s, cols_s, vals_s, Es,
                                 rows_t, cols_t, vals_t, Et, gamma, out);
}

// round 13
// speedup vs baseline: 1.8642x; 1.8642x over previous
#include <cuda_runtime.h>
#include <cstddef>
#include <cstdint>

// FusionAdjacency: Af = rownorm( sigmoid(g)*scatter(s) + (1-sigmoid(g))*scatter(t) )
//
// R11: concurrent TMA fill + L2-park fill.
//  K1 (one wave, homogeneous): per block, the elected thread grid-strides
//      cp.async.bulk 16KB zero-stores over rows [0,TROWS) (DRAM-paced, no SM
//      issue cost); ALL threads fold the hist REDs and plain-store-fill rows
//      [TROWS,NN) whose dirty lines PARK in the 126MB L2 (no DRAM writeback
//      during K1). DRAM never idles.
//  K2: rowinv = guarded reciprocal; re-zero rowsum (graph-replay safe).
//  K3: scatter all edges; park-region atomics are L2 hits; the 96MB parked
//      writeback drains underneath the latency-bound scatter.

#define NN     8192
#define TROWS  5120                                  // TMA region rows
#define STAGE  16384                                 // 16KB smem staging
#define TMA_BYTES ((long long)TROWS * NN * 4)        // 160 MB
#define NCHUNKS  ((int)(TMA_BYTES / STAGE))          // 10240

__device__ float g_rowsum[NN];  // zero at module load; K2 re-zeros each call
__device__ float g_rowinv[NN];

__device__ __forceinline__ uint32_t smem_u32(const void* p) {
    uint32_t a;
    asm("{ .reg .u64 t; cvta.to.shared.u64 t, %1; cvt.u32.u64 %0, t; }"
        : "=r"(a) : "l"(p));
    return a;
}

// ---------------------------------------------------------------- K1
__global__ __launch_bounds__(256) void k1_fill(
        const int* __restrict__ rows_s, const float* __restrict__ vals_s, int Es,
        const int* __restrict__ rows_t, const float* __restrict__ vals_t, int Et,
        const float* __restrict__ gamma, float* __restrict__ out) {
    __shared__ __align__(128) float4 stage[STAGE / 16];

    const int tid = blockIdx.x * blockDim.x + threadIdx.x;
    const int stride = gridDim.x * blockDim.x;
    const float4 z = make_float4(0.f, 0.f, 0.f, 0.f);

    // zero the 16KB staging buffer (1024 float4 / 256 threads = 4 each)
#pragma unroll
    for (int i = 0; i < 4; i++) stage[threadIdx.x + i * 256] = z;
    __syncthreads();
    asm volatile("fence.proxy.async.shared::cta;" ::: "memory");

    // (a) elected thread: grid-stride TMA bulk zero-stores over [0,TROWS)
    if (threadIdx.x == 0) {
        const uint32_t saddr = smem_u32(stage);
        char* gbase = reinterpret_cast<char*>(out);
        for (int ch = blockIdx.x; ch < NCHUNKS; ch += gridDim.x) {
            asm volatile(
                "cp.async.bulk.global.shared::cta.bulk_group [%0], [%1], %2;"
                :: "l"(gbase + (long long)ch * STAGE), "r"(saddr),
                   "r"((uint32_t)STAGE)
                : "memory");
        }
        asm volatile("cp.async.bulk.commit_group;" ::: "memory");
    }

    // (b) hist fold: fire-and-forget REDs into 32KB L2-hot region
    const float g = gamma[0];
    const float alpha = 1.0f / (1.0f + expf(-g));
    const float beta = 1.0f - alpha;
    for (int e = tid; e < Es; e += stride)
        atomicAdd(&g_rowsum[__ldg(&rows_s[e])], alpha * __ldg(&vals_s[e]));
    for (int e = tid; e < Et; e += stride)
        atomicAdd(&g_rowsum[__ldg(&rows_t[e])], beta * __ldg(&vals_t[e]));

    // (c) park fill: plain stores over rows [TROWS,NN) -> dirty lines stay
    //     in L2; writeback deferred past kernel end (drains under K3)
    {
        float4* out4 = reinterpret_cast<float4*>(out + (size_t)TROWS * NN);
        const int n4 = (NN - TROWS) * (NN / 4);
        for (int i = tid; i < n4; i += stride) out4[i] = z;
    }

    // ensure this block's bulk stores completed before retiring
    if (threadIdx.x == 0) {
        asm volatile("cp.async.bulk.wait_group 0;" ::: "memory");
    }
}

// ---------------------------------------------------------------- K2
__global__ void k2_finalize() {
    int i = blockIdx.x * blockDim.x + threadIdx.x;
    if (i < NN) {
        float s = g_rowsum[i];
        g_rowinv[i] = (s == 0.0f) ? 1.0f : (1.0f / s);
        g_rowsum[i] = 0.0f;   // ready for next graph replay
    }
}

// ---------------------------------------------------------------- K3
__global__ __launch_bounds__(256) void k3_scatter(
        const int* __restrict__ rows_s, const int* __restrict__ cols_s,
        const float* __restrict__ vals_s, int Es,
        const int* __restrict__ rows_t, const int* __restrict__ cols_t,
        const float* __restrict__ vals_t, int Et,
        const float* __restrict__ gamma, float* __restrict__ out) {
    const float g = gamma[0];
    const float alpha = 1.0f / (1.0f + expf(-g));
    const float beta = 1.0f - alpha;
    const int tid = blockIdx.x * blockDim.x + threadIdx.x;
    const int stride = gridDim.x * blockDim.x;

    const int n = (Es > Et) ? Es : Et;
    for (int e = tid; e < n; e += stride) {
        int rs = 0, cs = 0;  float vs = 0.0f;
        if (e < Es) {
            rs = __ldg(&rows_s[e]);
            cs = __ldg(&cols_s[e]);
            vs = __ldg(&vals_s[e]);
        }
        int rt = 0, ct = 0;  float vt = 0.0f;
        if (e < Et) {
            rt = __ldg(&rows_t[e]);
            ct = __ldg(&cols_t[e]);
            vt = __ldg(&vals_t[e]);
        }
        float invs = g_rowinv[rs];
        float invt = g_rowinv[rt];
        if (e < Es) atomicAdd(&out[((size_t)rs << 13) + cs], alpha * vs * invs);
        if (e < Et) atomicAdd(&out[((size_t)rt << 13) + ct], beta * vt * invt);
    }
}

// ---------------------------------------------------------------- launch
extern "C" void kernel_launch(void* const* d_in, const int* in_sizes, int n_in,
                              void* d_out, int out_size) {
    const int*   rows_s = (const int*)d_in[0];
    const int*   cols_s = (const int*)d_in[1];
    const float* vals_s = (const float*)d_in[2];
    const int*   rows_t = (const int*)d_in[3];
    const int*   cols_t = (const int*)d_in[4];
    const float* vals_t = (const float*)d_in[5];
    const float* gamma  = (const float*)d_in[6];
    float* out = (float*)d_out;

    const int Es = in_sizes[0];
    const int Et = in_sizes[3];

    // one full resident wave: 148 SMs x 8 blocks of 256 threads
    k1_fill<<<1184, 256>>>(rows_s, vals_s, Es, rows_t, vals_t, Et,
                           gamma, out);

    k2_finalize<<<(NN + 255) / 256, 256>>>();

    k3_scatter<<<1184, 256>>>(rows_s, cols_s, vals_s, Es,
                              rows_t, cols_t, vals_t, Et, gamma, out);
}